// round 11
// baseline (speedup 1.0000x reference)
#include <cuda_runtime.h>
#include <cuda_bf16.h>
#include <math.h>
#include <stdint.h>

#define D 50
#define E 300
#define KNB 63
#define NMAX 20000
#define BROW 80
#define JP 72              // padded j-row (bf16) for mma tiles; 144B stride

// ---------------- device scratch ----------------
__device__ __align__(16) float g_ent[NMAX * D];
__device__ __align__(16) float g_node[NMAX * D];
__device__ __align__(16) float g_WpT2[E * BROW];
__device__ __align__(1024) __nv_bfloat16 g_Bh2[D * 64 * JP];  // [i][o][j] hi
__device__ __align__(1024) __nv_bfloat16 g_Bl2[D * 64 * JP];  // [i][o][j] lo

// ---------------- helpers ----------------
__device__ __forceinline__ uint32_t smem_u32(const void* p) {
    uint32_t a;
    asm("{ .reg .u64 t; cvta.to.shared.u64 t, %1; cvt.u32.u64 %0, t; }" : "=r"(a) : "l"(p));
    return a;
}
#define LDSM_X4(r0, r1, r2, r3, addr)                                        \
    asm volatile("ldmatrix.sync.aligned.m8n8.x4.shared.b16 {%0,%1,%2,%3}, [%4];" \
        : "=r"(r0), "=r"(r1), "=r"(r2), "=r"(r3) : "r"(addr))
#define MMA16816(c, a, b0, b1)                                               \
    asm volatile("mma.sync.aligned.m16n8k16.row.col.f32.bf16.bf16.f32 "      \
        "{%0,%1,%2,%3}, {%4,%5,%6,%7}, {%8,%9}, {%0,%1,%2,%3};"              \
        : "+f"((c)[0]), "+f"((c)[1]), "+f"((c)[2]), "+f"((c)[3])             \
        : "r"((a)[0]), "r"((a)[1]), "r"((a)[2]), "r"((a)[3]), "r"(b0), "r"(b1))

// ---- f32x2 helpers (ent_proj) ----
__device__ __forceinline__ void fma2(unsigned long long& acc,
                                     unsigned long long a, unsigned long long b) {
    asm("fma.rn.f32x2 %0, %1, %2, %0;" : "+l"(acc) : "l"(a), "l"(b));
}
__device__ __forceinline__ unsigned long long dup2(float x) {
    unsigned long long r;
    asm("mov.b64 %0, {%1, %1};" : "=l"(r) : "f"(x));
    return r;
}
__device__ __forceinline__ float2 unpack2(unsigned long long v) {
    float2 r;
    asm("mov.b64 {%0, %1}, %2;" : "=f"(r.x), "=f"(r.y) : "l"(v));
    return r;
}

// smem layout for bil_mma (all offsets 16B-aligned)
#define SM_ES 0                            // float[128*52]   26624 B
#define SM_QS (128 * 52 * 4)               // float[50*128]   25600 B
#define SM_AH (SM_QS + 50 * 128 * 4)       // bf16[128*72]    18432 B
#define SM_AL (SM_AH + 128 * JP * 2)
#define SM_BH (SM_AL + 128 * JP * 2)       // bf16[64*72]      9216 B
#define SM_BL (SM_BH + 64 * JP * 2)
#define SM_TOT (SM_BL + 64 * JP * 2)       // 107520 B

// ============================================================
// Prep 1: Wp transpose (for ent_proj)
// ============================================================
__global__ void prep_kernel(const float* __restrict__ Wp) {
    int idx = blockIdx.x * blockDim.x + threadIdx.x;
    if (idx < E * BROW) {
        int k = idx / BROW, col = idx % BROW;
        int og = col / 20, cc = col % 20;
        int o = og * 16 + cc;
        g_WpT2[idx] = (cc < 16 && o < D) ? Wp[o * E + k] : 0.f;
    }
}

// ============================================================
// Prep 2: Wbil -> hi/lo bf16, layout [i][o][j] with j padded to 72
// hi = fp32 truncated to top 16 bits (exact Dekker head), lo = rn(v - hi)
// ============================================================
__global__ void prep_b_kernel(const float* __restrict__ Wbil) {
    int idx = blockIdx.x * blockDim.x + threadIdx.x;
    if (idx >= D * 64 * JP) return;
    int i = idx / (64 * JP);
    int rem = idx % (64 * JP);
    int o = rem / JP, j = rem % JP;
    float v = (o < D && j < D) ? Wbil[o * (D * D) + i * D + j] : 0.f;
    uint32_t ub = __float_as_uint(v);
    g_Bh2[idx] = __ushort_as_bfloat16((unsigned short)(ub >> 16));
    float hif = __uint_as_float(ub & 0xFFFF0000u);
    g_Bl2[idx] = __float2bfloat16(v - hif);
}

// ============================================================
// Kernel A: ent = entity @ Wp^T + bp (f32x2 packed, proven, unchanged)
// ============================================================
__global__ __launch_bounds__(128) void ent_proj_kernel(
    const float* __restrict__ entity, const float* __restrict__ bp, int N) {
    __shared__ __align__(16) float As[50 * 66];
    __shared__ __align__(16) float Bs[50 * BROW];
    int tid = threadIdx.x;
    int ng = tid >> 2, og = tid & 3;
    int n0 = blockIdx.x * 64;

    unsigned long long acc[2][8];
    #pragma unroll
    for (int s = 0; s < 2; s++)
        #pragma unroll
        for (int p = 0; p < 8; p++) acc[s][p] = 0ull;

    for (int c0 = 0; c0 < E; c0 += 50) {
        __syncthreads();
        for (int idx = tid; idx < 64 * 50; idx += 128) {
            int n = idx / 50, k = idx % 50;
            int gn = n0 + n;
            As[k * 66 + n] = (gn < N) ? entity[(size_t)gn * E + c0 + k] : 0.f;
        }
        for (int idx = tid; idx < 50 * BROW / 4; idx += 128)
            ((float4*)Bs)[idx] = ((const float4*)(g_WpT2 + (size_t)c0 * BROW))[idx];
        __syncthreads();
        #pragma unroll 10
        for (int k = 0; k < 50; k++) {
            float2 ap = *(const float2*)&As[k * 66 + 2 * ng];
            unsigned long long aA = dup2(ap.x), aB = dup2(ap.y);
            const ulonglong2* bpp = (const ulonglong2*)&Bs[k * BROW + og * 20];
            ulonglong2 u0 = bpp[0], u1 = bpp[1], u2 = bpp[2], u3 = bpp[3];
            fma2(acc[0][0], aA, u0.x); fma2(acc[0][1], aA, u0.y);
            fma2(acc[0][2], aA, u1.x); fma2(acc[0][3], aA, u1.y);
            fma2(acc[0][4], aA, u2.x); fma2(acc[0][5], aA, u2.y);
            fma2(acc[0][6], aA, u3.x); fma2(acc[0][7], aA, u3.y);
            fma2(acc[1][0], aB, u0.x); fma2(acc[1][1], aB, u0.y);
            fma2(acc[1][2], aB, u1.x); fma2(acc[1][3], aB, u1.y);
            fma2(acc[1][4], aB, u2.x); fma2(acc[1][5], aB, u2.y);
            fma2(acc[1][6], aB, u3.x); fma2(acc[1][7], aB, u3.y);
        }
    }
    #pragma unroll
    for (int s = 0; s < 2; s++) {
        int n = n0 + 2 * ng + s;
        if (n >= N) continue;
        #pragma unroll
        for (int p = 0; p < 8; p++) {
            int o = og * 16 + 2 * p;
            float2 v = unpack2(acc[s][p]);
            if (o < D)     g_ent[(size_t)n * D + o]     = v.x + bp[o];
            if (o + 1 < D) g_ent[(size_t)n * D + o + 1] = v.y + bp[o + 1];
        }
    }
}

// ============================================================
// Kernel B: bilinear as one register-accumulated warp-MMA GEMM.
// node[n,o] = sum_{i,j} (q[n,i]*ent[n,j]) * Wbil[o,i,j]
// M=128 nodes/block, N=64 (o pad), K = 50 i-iters x 64 j.
// A built per-i (fp32 product -> hi/lo bf16), 3-term MMA, C in regs.
// 256 threads = 8 warps (4 along M x 2 along N).
// ============================================================
__global__ __launch_bounds__(256) void bil_mma_kernel(
    const float* __restrict__ query, const float* __restrict__ bbil, int N) {
    extern __shared__ __align__(16) char smem[];
    float* es = (float*)(smem + SM_ES);           // [128][52]
    float* qs = (float*)(smem + SM_QS);           // [50][128]
    __nv_bfloat16* Ah = (__nv_bfloat16*)(smem + SM_AH);   // [128][72]
    __nv_bfloat16* Al = (__nv_bfloat16*)(smem + SM_AL);
    uint32_t sb = smem_u32(smem);

    int tid = threadIdx.x, lane = tid & 31, wid = tid >> 5;
    int wm = wid & 3, wn = wid >> 2;     // warp tile: rows wm*32, cols wn*32
    int n0 = blockIdx.x * 128;

    // load ent + query tiles (coalesced over D)
    for (int idx = tid; idx < 128 * D; idx += 256) {
        int n = idx / D, x = idx % D;
        int gn = n0 + n;
        float ev = (gn < N) ? g_ent[(size_t)gn * D + x] : 0.f;
        float qv = (gn < N) ? query[(size_t)gn * D + x] : 0.f;
        es[n * 52 + x] = ev;
        qs[x * 128 + n] = qv;
    }
    // zero A pad columns j in [50,72) once (never rewritten)
    for (int idx = tid; idx < 128 * (JP - D); idx += 256) {
        int n = idx / (JP - D), j = D + idx % (JP - D);
        Ah[n * JP + j] = __ushort_as_bfloat16(0);
        Al[n * JP + j] = __ushort_as_bfloat16(0);
    }

    float C[2][4][4];
    #pragma unroll
    for (int mf = 0; mf < 2; mf++)
        #pragma unroll
        for (int nf = 0; nf < 4; nf++)
            #pragma unroll
            for (int r = 0; r < 4; r++) C[mf][nf][r] = 0.f;

    int an = tid >> 1;              // node row this thread builds
    int aj0 = (tid & 1) * 25;       // j sub-range

    for (int i = 0; i < D; i++) {
        __syncthreads();            // previous iter's ldmatrix done
        // ---- build A_i = q[:,i] * ent, split hi/lo ----
        {
            float q = qs[i * 128 + an];
            const float* erow = &es[an * 52];
            __nv_bfloat16* ahr = &Ah[an * JP];
            __nv_bfloat16* alr = &Al[an * JP];
            #pragma unroll 5
            for (int jj = 0; jj < 25; jj++) {
                int j = aj0 + jj;
                float p = q * erow[j];
                uint32_t ub = __float_as_uint(p);
                ahr[j] = __ushort_as_bfloat16((unsigned short)(ub >> 16));
                float hif = __uint_as_float(ub & 0xFFFF0000u);
                alr[j] = __float2bfloat16(p - hif);
            }
        }
        // ---- copy B_i (flat float4 stream, L2-resident) ----
        {
            const float4* sh = (const float4*)(g_Bh2 + (size_t)i * (64 * JP));
            const float4* sl = (const float4*)(g_Bl2 + (size_t)i * (64 * JP));
            float4* dh = (float4*)(smem + SM_BH);
            float4* dl = (float4*)(smem + SM_BL);
            for (int c = tid; c < 64 * JP * 2 / 16; c += 256) {
                dh[c] = sh[c];
                dl[c] = sl[c];
            }
        }
        __syncthreads();

        // ---- ldmatrix + 3-term mma over K=64 (4 k-steps) ----
        #pragma unroll
        for (int kf = 0; kf < 4; kf++) {
            uint32_t ah[2][4], al[2][4], bh[2][4], bl[2][4];
            #pragma unroll
            for (int mf = 0; mf < 2; mf++) {
                int row = wm * 32 + mf * 16 + (lane & 15);
                int col = kf * 16 + (lane >> 4) * 8;
                uint32_t off = (uint32_t)(row * JP + col) * 2;
                LDSM_X4(ah[mf][0], ah[mf][1], ah[mf][2], ah[mf][3], sb + SM_AH + off);
                LDSM_X4(al[mf][0], al[mf][1], al[mf][2], al[mf][3], sb + SM_AL + off);
            }
            #pragma unroll
            for (int np = 0; np < 2; np++) {
                int row = wn * 32 + np * 16 + (lane >> 4) * 8 + (lane & 7);
                int col = kf * 16 + ((lane >> 3) & 1) * 8;
                uint32_t off = (uint32_t)(row * JP + col) * 2;
                LDSM_X4(bh[np][0], bh[np][1], bh[np][2], bh[np][3], sb + SM_BH + off);
                LDSM_X4(bl[np][0], bl[np][1], bl[np][2], bl[np][3], sb + SM_BL + off);
            }
            #pragma unroll
            for (int mf = 0; mf < 2; mf++)
                #pragma unroll
                for (int nf = 0; nf < 4; nf++) {
                    int np = nf >> 1, pb = (nf & 1) * 2;
                    MMA16816(C[mf][nf], ah[mf], bh[np][pb], bh[np][pb + 1]);
                    MMA16816(C[mf][nf], ah[mf], bl[np][pb], bl[np][pb + 1]);
                    MMA16816(C[mf][nf], al[mf], bh[np][pb], bh[np][pb + 1]);
                }
        }
    }

    // ---- epilogue: write node (+bbil) ----
    #pragma unroll
    for (int mf = 0; mf < 2; mf++)
        #pragma unroll
        for (int nf = 0; nf < 4; nf++)
            #pragma unroll
            for (int r = 0; r < 4; r++) {
                int m = wm * 32 + mf * 16 + (lane >> 2) + ((r >= 2) ? 8 : 0);
                int col = wn * 32 + nf * 8 + 2 * (lane & 3) + (r & 1);
                int gn = n0 + m;
                if (col < D && gn < N)
                    g_node[(size_t)gn * D + col] = C[mf][nf][r] + bbil[col];
            }
}

// ============================================================
// Kernel C: fused tail (proven structure; g_node complete w/ bbil)
// ============================================================
__global__ __launch_bounds__(256) void tail_kernel(
    const float* __restrict__ nbr, const float* __restrict__ scores,
    const float* __restrict__ Wg, const float* __restrict__ g_bias,
    const float* __restrict__ Wr, const float* __restrict__ br,
    float* __restrict__ out, int N) {
    __shared__ __align__(16) float Wgs[50 * 51];
    __shared__ __align__(16) float s_sm[8][50];
    __shared__ __align__(16) float Wrs[50];
    __shared__ __align__(16) float gbs[50];
    int tid = threadIdx.x;

    for (int idx = tid; idx < 2500; idx += 256) {
        int o = idx / 50, d = idx % 50;
        Wgs[o * 51 + d] = Wg[idx];
    }
    if (tid < 50) { Wrs[tid] = Wr[tid]; gbs[tid] = g_bias[tid]; }
    __syncthreads();

    int warp = tid >> 5, lane = tid & 31;
    int n = blockIdx.x * 8 + warp;
    if (n >= N) return;

    const float* base = nbr + (size_t)n * KNB * D;
    const float* sc   = scores + (size_t)n * (KNB + 1);

    if (lane < 25) {
        float wK = sc[KNB];
        float2 v = *(const float2*)&g_node[(size_t)n * D + 2 * lane];
        float sx = wK * v.x, sy = wK * v.y;
        float tx_ = 0.f, ty_ = 0.f;
        #pragma unroll
        for (int k = 0; k < 62; k += 2) {
            float w0 = sc[k], w1 = sc[k + 1];
            float2 u0 = *(const float2*)(base + (size_t)k * D + 2 * lane);
            float2 u1 = *(const float2*)(base + (size_t)(k + 1) * D + 2 * lane);
            sx += w0 * u0.x; sy += w0 * u0.y;
            tx_ += w1 * u1.x; ty_ += w1 * u1.y;
        }
        {
            float w = sc[62];
            float2 u = *(const float2*)(base + (size_t)62 * D + 2 * lane);
            sx += w * u.x; sy += w * u.y;
        }
        s_sm[warp][2 * lane]     = sx + tx_;
        s_sm[warp][2 * lane + 1] = sy + ty_;
    }
    __syncwarp();

    float r = 0.f;
    #pragma unroll
    for (int rep = 0; rep < 2; rep++) {
        int o = lane + 32 * rep;
        if (o < D) {
            float a = gbs[o];
            #pragma unroll 10
            for (int d = 0; d < D; d++)
                a += s_sm[warp][d] * Wgs[o * 51 + d];
            float f = (a > 0.f) ? a : expm1f(a);
            r += f * Wrs[o];
        }
    }
    #pragma unroll
    for (int off = 16; off; off >>= 1)
        r += __shfl_down_sync(0xffffffffu, r, off);
    if (lane == 0) out[n] = r + br[0];
}

// ============================================================
extern "C" void kernel_launch(void* const* d_in, const int* in_sizes, int n_in,
                              void* d_out, int out_size) {
    const float* query  = (const float*)d_in[0];
    const float* entity = (const float*)d_in[1];
    const float* nbr    = (const float*)d_in[2];
    const float* scores = (const float*)d_in[3];
    const float* Wp     = (const float*)d_in[4];
    const float* bp     = (const float*)d_in[5];
    const float* Wbil   = (const float*)d_in[6];
    const float* bbil   = (const float*)d_in[7];
    const float* Wg     = (const float*)d_in[8];
    const float* gbias  = (const float*)d_in[9];
    const float* Wr     = (const float*)d_in[10];
    const float* br     = (const float*)d_in[11];
    float* out = (float*)d_out;

    int N = in_sizes[0] / D;
    if (N > NMAX) N = NMAX;

    static bool attr_set = false;
    if (!attr_set) {
        cudaFuncSetAttribute(bil_mma_kernel,
                             cudaFuncAttributeMaxDynamicSharedMemorySize, SM_TOT);
        attr_set = true;
    }

    prep_kernel<<<(E * BROW + 255) / 256, 256>>>(Wp);
    prep_b_kernel<<<(D * 64 * JP + 255) / 256, 256>>>(Wbil);
    ent_proj_kernel<<<(N + 63) / 64, 128>>>(entity, bp, N);
    bil_mma_kernel<<<(N + 127) / 128, 256, SM_TOT>>>(query, bbil, N);
    tail_kernel<<<(N + 7) / 8, 256>>>(nbr, scores, Wg, gbias, Wr, br, out, N);
}

// round 12
// speedup vs baseline: 1.7769x; 1.7769x over previous
#include <cuda_runtime.h>
#include <cuda_bf16.h>
#include <math.h>
#include <stdint.h>

#define D 50
#define E 300
#define KNB 63
#define NMAX 20000
#define BROW 80
#define JP 72              // padded j-row (bf16); 144B stride -> conflict-free ldsm

// ---------------- device scratch ----------------
__device__ __align__(16) float g_ent[NMAX * D];
__device__ __align__(16) float g_node[NMAX * D];
__device__ __align__(16) float g_WpT2[E * BROW];
__device__ __align__(1024) __nv_bfloat16 g_Bh2[D * 64 * JP];  // [i][o][j] hi
__device__ __align__(1024) __nv_bfloat16 g_Bl2[D * 64 * JP];  // [i][o][j] lo

// ---------------- helpers ----------------
__device__ __forceinline__ uint32_t smem_u32(const void* p) {
    uint32_t a;
    asm("{ .reg .u64 t; cvta.to.shared.u64 t, %1; cvt.u32.u64 %0, t; }" : "=r"(a) : "l"(p));
    return a;
}
#define LDSM_X4(r0, r1, r2, r3, addr)                                        \
    asm volatile("ldmatrix.sync.aligned.m8n8.x4.shared.b16 {%0,%1,%2,%3}, [%4];" \
        : "=r"(r0), "=r"(r1), "=r"(r2), "=r"(r3) : "r"(addr))
#define MMA16816(c, a, b0, b1)                                               \
    asm volatile("mma.sync.aligned.m16n8k16.row.col.f32.bf16.bf16.f32 "      \
        "{%0,%1,%2,%3}, {%4,%5,%6,%7}, {%8,%9}, {%0,%1,%2,%3};"              \
        : "+f"((c)[0]), "+f"((c)[1]), "+f"((c)[2]), "+f"((c)[3])             \
        : "r"((a)[0]), "r"((a)[1]), "r"((a)[2]), "r"((a)[3]), "r"(b0), "r"(b1))

// ---- f32x2 helpers (ent_proj) ----
__device__ __forceinline__ void fma2(unsigned long long& acc,
                                     unsigned long long a, unsigned long long b) {
    asm("fma.rn.f32x2 %0, %1, %2, %0;" : "+l"(acc) : "l"(a), "l"(b));
}
__device__ __forceinline__ unsigned long long dup2(float x) {
    unsigned long long r;
    asm("mov.b64 %0, {%1, %1};" : "=l"(r) : "f"(x));
    return r;
}
__device__ __forceinline__ float2 unpack2(unsigned long long v) {
    float2 r;
    asm("mov.b64 {%0, %1}, %2;" : "=f"(r.x), "=f"(r.y) : "l"(v));
    return r;
}

// smem layout for bil_mma: qs | Ah | Al | B double buffer (all 16B aligned)
#define SM_QS 0                              // float[50*64]  = 12800 B
#define SM_AH 12800                          // bf16[64*72]   =  9216 B
#define SM_AL (SM_AH + 64 * JP * 2)          // 22016
#define SM_B  (SM_AL + 64 * JP * 2)          // 31232; buf b: hi +b*18432, lo +9216
#define SM_TOT (SM_B + 2 * 2 * 64 * JP * 2)  // 68096 B

// ============================================================
// Prep 1: Wp transpose (for ent_proj)
// ============================================================
__global__ void prep_kernel(const float* __restrict__ Wp) {
    int idx = blockIdx.x * blockDim.x + threadIdx.x;
    if (idx < E * BROW) {
        int k = idx / BROW, col = idx % BROW;
        int og = col / 20, cc = col % 20;
        int o = og * 16 + cc;
        g_WpT2[idx] = (cc < 16 && o < D) ? Wp[o * E + k] : 0.f;
    }
}

// ============================================================
// Prep 2: Wbil -> hi/lo bf16, layout [i][o][j], j padded to 72
// ============================================================
__global__ void prep_b_kernel(const float* __restrict__ Wbil) {
    int idx = blockIdx.x * blockDim.x + threadIdx.x;
    if (idx >= D * 64 * JP) return;
    int i = idx / (64 * JP);
    int rem = idx % (64 * JP);
    int o = rem / JP, j = rem % JP;
    float v = (o < D && j < D) ? Wbil[o * (D * D) + i * D + j] : 0.f;
    uint32_t ub = __float_as_uint(v);
    g_Bh2[idx] = __ushort_as_bfloat16((unsigned short)(ub >> 16));
    float hif = __uint_as_float(ub & 0xFFFF0000u);
    g_Bl2[idx] = __float2bfloat16(v - hif);
}

// ============================================================
// Kernel A: ent = entity @ Wp^T + bp (f32x2 packed, proven, unchanged)
// ============================================================
__global__ __launch_bounds__(128) void ent_proj_kernel(
    const float* __restrict__ entity, const float* __restrict__ bp, int N) {
    __shared__ __align__(16) float As[50 * 66];
    __shared__ __align__(16) float Bs[50 * BROW];
    int tid = threadIdx.x;
    int ng = tid >> 2, og = tid & 3;
    int n0 = blockIdx.x * 64;

    unsigned long long acc[2][8];
    #pragma unroll
    for (int s = 0; s < 2; s++)
        #pragma unroll
        for (int p = 0; p < 8; p++) acc[s][p] = 0ull;

    for (int c0 = 0; c0 < E; c0 += 50) {
        __syncthreads();
        for (int idx = tid; idx < 64 * 50; idx += 128) {
            int n = idx / 50, k = idx % 50;
            int gn = n0 + n;
            As[k * 66 + n] = (gn < N) ? entity[(size_t)gn * E + c0 + k] : 0.f;
        }
        for (int idx = tid; idx < 50 * BROW / 4; idx += 128)
            ((float4*)Bs)[idx] = ((const float4*)(g_WpT2 + (size_t)c0 * BROW))[idx];
        __syncthreads();
        #pragma unroll 10
        for (int k = 0; k < 50; k++) {
            float2 ap = *(const float2*)&As[k * 66 + 2 * ng];
            unsigned long long aA = dup2(ap.x), aB = dup2(ap.y);
            const ulonglong2* bpp = (const ulonglong2*)&Bs[k * BROW + og * 20];
            ulonglong2 u0 = bpp[0], u1 = bpp[1], u2 = bpp[2], u3 = bpp[3];
            fma2(acc[0][0], aA, u0.x); fma2(acc[0][1], aA, u0.y);
            fma2(acc[0][2], aA, u1.x); fma2(acc[0][3], aA, u1.y);
            fma2(acc[0][4], aA, u2.x); fma2(acc[0][5], aA, u2.y);
            fma2(acc[0][6], aA, u3.x); fma2(acc[0][7], aA, u3.y);
            fma2(acc[1][0], aB, u0.x); fma2(acc[1][1], aB, u0.y);
            fma2(acc[1][2], aB, u1.x); fma2(acc[1][3], aB, u1.y);
            fma2(acc[1][4], aB, u2.x); fma2(acc[1][5], aB, u2.y);
            fma2(acc[1][6], aB, u3.x); fma2(acc[1][7], aB, u3.y);
        }
    }
    #pragma unroll
    for (int s = 0; s < 2; s++) {
        int n = n0 + 2 * ng + s;
        if (n >= N) continue;
        #pragma unroll
        for (int p = 0; p < 8; p++) {
            int o = og * 16 + 2 * p;
            float2 v = unpack2(acc[s][p]);
            if (o < D)     g_ent[(size_t)n * D + o]     = v.x + bp[o];
            if (o + 1 < D) g_ent[(size_t)n * D + o + 1] = v.y + bp[o + 1];
        }
    }
}

// ============================================================
// Kernel B v2: A (ent hi/lo) loop-invariant; per-i chunk:
//   D_i = ent @ W_i^T via 3-term bf16 MMA; acc += q[:,i] * D_i (registers).
// M=64 nodes, N=64 o-pad, 256 threads = 8 warps (wm in {0,1} x wn in {0..3}).
// B double-buffered, ONE sync per chunk.
// ============================================================
__global__ __launch_bounds__(256) void bil_mma_kernel(
    const float* __restrict__ query, const float* __restrict__ bbil, int N) {
    extern __shared__ __align__(16) char smem[];
    float* qs = (float*)(smem + SM_QS);                 // [50][64]
    __nv_bfloat16* Ah = (__nv_bfloat16*)(smem + SM_AH); // [64][72]
    __nv_bfloat16* Al = (__nv_bfloat16*)(smem + SM_AL);
    uint32_t sb = smem_u32(smem);

    int tid = threadIdx.x, lane = tid & 31, wid = tid >> 5;
    int wm = wid & 1, wn = wid >> 1;   // rows wm*32, cols wn*16
    int n0 = blockIdx.x * 64;

    // ---- one-time loads: q tile, A = ent hi/lo ----
    for (int idx = tid; idx < 64 * D; idx += 256) {
        int n = idx / D, x = idx % D;
        int gn = n0 + n;
        float qv = (gn < N) ? query[(size_t)gn * D + x] : 0.f;
        float ev = (gn < N) ? g_ent[(size_t)gn * D + x] : 0.f;
        qs[x * 64 + n] = qv;
        uint32_t ub = __float_as_uint(ev);
        Ah[n * JP + x] = __ushort_as_bfloat16((unsigned short)(ub >> 16));
        Al[n * JP + x] = __float2bfloat16(ev - __uint_as_float(ub & 0xFFFF0000u));
    }
    for (int idx = tid; idx < 64 * (JP - D); idx += 256) {
        int n = idx / (JP - D), j = D + idx % (JP - D);
        Ah[n * JP + j] = __ushort_as_bfloat16(0);
        Al[n * JP + j] = __ushort_as_bfloat16(0);
    }
    // prime B buffer 0 with chunk i=0
    {
        const float4* sh = (const float4*)g_Bh2;
        const float4* sl = (const float4*)g_Bl2;
        float4* dh = (float4*)(smem + SM_B);
        float4* dl = (float4*)(smem + SM_B + 9216);
        for (int c = tid; c < 64 * JP * 2 / 16; c += 256) { dh[c] = sh[c]; dl[c] = sl[c]; }
    }
    __syncthreads();

    float acc[2][2][4];
    #pragma unroll
    for (int mf = 0; mf < 2; mf++)
        #pragma unroll
        for (int nf = 0; nf < 2; nf++)
            #pragma unroll
            for (int r = 0; r < 4; r++) acc[mf][nf][r] = 0.f;

    for (int i = 0; i < D; i++) {
        int cur = i & 1;
        // issue next chunk's copy early (targets other buffer; completes by next sync)
        if (i + 1 < D) {
            const float4* sh = (const float4*)(g_Bh2 + (size_t)(i + 1) * (64 * JP));
            const float4* sl = (const float4*)(g_Bl2 + (size_t)(i + 1) * (64 * JP));
            float4* dh = (float4*)(smem + SM_B + (cur ^ 1) * 18432);
            float4* dl = (float4*)(smem + SM_B + (cur ^ 1) * 18432 + 9216);
            for (int c = tid; c < 64 * JP * 2 / 16; c += 256) { dh[c] = sh[c]; dl[c] = sl[c]; }
        }

        uint32_t bbase = sb + SM_B + cur * 18432;
        float C[2][2][4];
        #pragma unroll
        for (int mf = 0; mf < 2; mf++)
            #pragma unroll
            for (int nf = 0; nf < 2; nf++)
                #pragma unroll
                for (int r = 0; r < 4; r++) C[mf][nf][r] = 0.f;

        #pragma unroll
        for (int kf = 0; kf < 4; kf++) {
            uint32_t ah[2][4], al[2][4], bh[4], bl[4];
            #pragma unroll
            for (int mf = 0; mf < 2; mf++) {
                int row = wm * 32 + mf * 16 + (lane & 15);
                int col = kf * 16 + (lane >> 4) * 8;
                uint32_t off = (uint32_t)(row * JP + col) * 2;
                LDSM_X4(ah[mf][0], ah[mf][1], ah[mf][2], ah[mf][3], sb + SM_AH + off);
                LDSM_X4(al[mf][0], al[mf][1], al[mf][2], al[mf][3], sb + SM_AL + off);
            }
            {
                int row = wn * 16 + (lane >> 4) * 8 + (lane & 7);
                int col = kf * 16 + ((lane >> 3) & 1) * 8;
                uint32_t off = (uint32_t)(row * JP + col) * 2;
                LDSM_X4(bh[0], bh[1], bh[2], bh[3], bbase + off);
                LDSM_X4(bl[0], bl[1], bl[2], bl[3], bbase + 9216 + off);
            }
            #pragma unroll
            for (int mf = 0; mf < 2; mf++)
                #pragma unroll
                for (int nf = 0; nf < 2; nf++) {
                    int pb = nf * 2;
                    MMA16816(C[mf][nf], ah[mf], bh[pb], bh[pb + 1]);
                    MMA16816(C[mf][nf], ah[mf], bl[pb], bl[pb + 1]);
                    MMA16816(C[mf][nf], al[mf], bh[pb], bh[pb + 1]);
                }
        }

        // epilogue: acc += q[n,i] * C  (rows m0, m0+8 per mf)
        #pragma unroll
        for (int mf = 0; mf < 2; mf++) {
            int m0 = wm * 32 + mf * 16 + (lane >> 2);
            float q0 = qs[i * 64 + m0];
            float q1 = qs[i * 64 + m0 + 8];
            #pragma unroll
            for (int nf = 0; nf < 2; nf++) {
                acc[mf][nf][0] += q0 * C[mf][nf][0];
                acc[mf][nf][1] += q0 * C[mf][nf][1];
                acc[mf][nf][2] += q1 * C[mf][nf][2];
                acc[mf][nf][3] += q1 * C[mf][nf][3];
            }
        }
        __syncthreads();   // next buffer filled; cur buffer free for overwrite next+1
    }

    // ---- write node (+bbil) ----
    #pragma unroll
    for (int mf = 0; mf < 2; mf++)
        #pragma unroll
        for (int nf = 0; nf < 2; nf++)
            #pragma unroll
            for (int r = 0; r < 4; r++) {
                int m = wm * 32 + mf * 16 + (lane >> 2) + ((r >= 2) ? 8 : 0);
                int col = wn * 16 + nf * 8 + 2 * (lane & 3) + (r & 1);
                int gn = n0 + m;
                if (col < D && gn < N)
                    g_node[(size_t)gn * D + col] = acc[mf][nf][r] + bbil[col];
            }
}

// ============================================================
// Kernel C: fused tail (proven structure; g_node complete w/ bbil)
// ============================================================
__global__ __launch_bounds__(256) void tail_kernel(
    const float* __restrict__ nbr, const float* __restrict__ scores,
    const float* __restrict__ Wg, const float* __restrict__ g_bias,
    const float* __restrict__ Wr, const float* __restrict__ br,
    float* __restrict__ out, int N) {
    __shared__ __align__(16) float Wgs[50 * 51];
    __shared__ __align__(16) float s_sm[8][50];
    __shared__ __align__(16) float Wrs[50];
    __shared__ __align__(16) float gbs[50];
    int tid = threadIdx.x;

    for (int idx = tid; idx < 2500; idx += 256) {
        int o = idx / 50, d = idx % 50;
        Wgs[o * 51 + d] = Wg[idx];
    }
    if (tid < 50) { Wrs[tid] = Wr[tid]; gbs[tid] = g_bias[tid]; }
    __syncthreads();

    int warp = tid >> 5, lane = tid & 31;
    int n = blockIdx.x * 8 + warp;
    if (n >= N) return;

    const float* base = nbr + (size_t)n * KNB * D;
    const float* sc   = scores + (size_t)n * (KNB + 1);

    if (lane < 25) {
        float wK = sc[KNB];
        float2 v = *(const float2*)&g_node[(size_t)n * D + 2 * lane];
        float sx = wK * v.x, sy = wK * v.y;
        float tx_ = 0.f, ty_ = 0.f;
        #pragma unroll
        for (int k = 0; k < 62; k += 2) {
            float w0 = sc[k], w1 = sc[k + 1];
            float2 u0 = *(const float2*)(base + (size_t)k * D + 2 * lane);
            float2 u1 = *(const float2*)(base + (size_t)(k + 1) * D + 2 * lane);
            sx += w0 * u0.x; sy += w0 * u0.y;
            tx_ += w1 * u1.x; ty_ += w1 * u1.y;
        }
        {
            float w = sc[62];
            float2 u = *(const float2*)(base + (size_t)62 * D + 2 * lane);
            sx += w * u.x; sy += w * u.y;
        }
        s_sm[warp][2 * lane]     = sx + tx_;
        s_sm[warp][2 * lane + 1] = sy + ty_;
    }
    __syncwarp();

    float r = 0.f;
    #pragma unroll
    for (int rep = 0; rep < 2; rep++) {
        int o = lane + 32 * rep;
        if (o < D) {
            float a = gbs[o];
            #pragma unroll 10
            for (int d = 0; d < D; d++)
                a += s_sm[warp][d] * Wgs[o * 51 + d];
            float f = (a > 0.f) ? a : expm1f(a);
            r += f * Wrs[o];
        }
    }
    #pragma unroll
    for (int off = 16; off; off >>= 1)
        r += __shfl_down_sync(0xffffffffu, r, off);
    if (lane == 0) out[n] = r + br[0];
}

// ============================================================
extern "C" void kernel_launch(void* const* d_in, const int* in_sizes, int n_in,
                              void* d_out, int out_size) {
    const float* query  = (const float*)d_in[0];
    const float* entity = (const float*)d_in[1];
    const float* nbr    = (const float*)d_in[2];
    const float* scores = (const float*)d_in[3];
    const float* Wp     = (const float*)d_in[4];
    const float* bp     = (const float*)d_in[5];
    const float* Wbil   = (const float*)d_in[6];
    const float* bbil   = (const float*)d_in[7];
    const float* Wg     = (const float*)d_in[8];
    const float* gbias  = (const float*)d_in[9];
    const float* Wr     = (const float*)d_in[10];
    const float* br     = (const float*)d_in[11];
    float* out = (float*)d_out;

    int N = in_sizes[0] / D;
    if (N > NMAX) N = NMAX;

    static bool attr_set = false;
    if (!attr_set) {
        cudaFuncSetAttribute(bil_mma_kernel,
                             cudaFuncAttributeMaxDynamicSharedMemorySize, SM_TOT);
        attr_set = true;
    }

    prep_kernel<<<(E * BROW + 255) / 256, 256>>>(Wp);
    prep_b_kernel<<<(D * 64 * JP + 255) / 256, 256>>>(Wbil);
    ent_proj_kernel<<<(N + 63) / 64, 128>>>(entity, bp, N);
    bil_mma_kernel<<<(N + 63) / 64, 256, SM_TOT>>>(query, bbil, N);
    tail_kernel<<<(N + 7) / 8, 256>>>(nbr, scores, Wg, gbias, Wr, br, out, N);
}